// round 6
// baseline (speedup 1.0000x reference)
#include <cuda_runtime.h>
#include <cuda_bf16.h>
#include <cstdint>

#define IN_F   512
#define OUT_F  512
#define BATCH  16384
#define BM     128
#define BN     128
#define NSP    32            // int8 spline steps (16 feats x 8 bases = 128 int8 K each)
#define NBASE  24            // bf16 base steps (8 kb x {hi*Whi, lo*Whi, hi*Wlo})
#define NSTEP  (NSP + NBASE) // 56
#define TILE   16384         // every tile: 128 rows x 128B
#define SP_BYTES  (NSP * TILE)            // 512 KB spline A per rowblock
#define RB_BYTES  (SP_BYTES + 16 * TILE)  // + 16 bf16 chunks (8 hi + 8 lo) = 768 KB
#define DYN    (6 * TILE + 1024)          // 3 A-buf + 3 B-buf

#define QA     190.5f                     // 127 / (2/3)
#define QAINV  ((2.0f / 3.0f) / 127.0f)

__device__ char  g_A[(size_t)128 * RB_BYTES];            // 96 MB
__device__ char  g_Wb[16 * OUT_F * 128];                 // bf16 base W, 1 MB
__device__ char  g_Ws[NSP * OUT_F * 128];                // int8 spline W, 2 MB
__device__ float g_sWinv[OUT_F];                         // per-column dequant

// ---------------- helpers ----------------
static __device__ __forceinline__ uint32_t smem_u32(const void* p) {
    uint32_t a;
    asm("{ .reg .u64 t; cvta.to.shared.u64 t, %1; cvt.u32.u64 %0, t; }" : "=r"(a) : "l"(p));
    return a;
}
static __device__ __forceinline__ void cp16(uint32_t dst, const void* src) {
    asm volatile("cp.async.cg.shared.global [%0], [%1], 16;" :: "r"(dst), "l"(src) : "memory");
}
#define CP_COMMIT() asm volatile("cp.async.commit_group;" ::: "memory")
#define CP_WAIT1()  asm volatile("cp.async.wait_group 1;" ::: "memory")

static __device__ __forceinline__ void ldsm4(uint32_t* r, uint32_t a) {
    asm volatile("ldmatrix.sync.aligned.m8n8.x4.shared.b16 {%0,%1,%2,%3}, [%4];"
                 : "=r"(r[0]), "=r"(r[1]), "=r"(r[2]), "=r"(r[3]) : "r"(a));
}
static __device__ __forceinline__ void mma_bf16(float* d, const uint32_t* a, const uint32_t* b) {
    asm volatile("mma.sync.aligned.m16n8k16.row.col.f32.bf16.bf16.f32 "
                 "{%0,%1,%2,%3}, {%4,%5,%6,%7}, {%8,%9}, {%0,%1,%2,%3};"
                 : "+f"(d[0]), "+f"(d[1]), "+f"(d[2]), "+f"(d[3])
                 : "r"(a[0]), "r"(a[1]), "r"(a[2]), "r"(a[3]), "r"(b[0]), "r"(b[1]));
}
static __device__ __forceinline__ void mma_s8(int* d, const uint32_t* a, const uint32_t* b) {
    asm volatile("mma.sync.aligned.m16n8k32.row.col.s32.s8.s8.s32 "
                 "{%0,%1,%2,%3}, {%4,%5,%6,%7}, {%8,%9}, {%0,%1,%2,%3};"
                 : "+r"(d[0]), "+r"(d[1]), "+r"(d[2]), "+r"(d[3])
                 : "r"(a[0]), "r"(a[1]), "r"(a[2]), "r"(a[3]), "r"(b[0]), "r"(b[1]));
}
static __device__ __forceinline__ uint32_t pk2(float lo, float hi) {
    uint32_t r; asm("cvt.rn.bf16x2.f32 %0, %1, %2;" : "=r"(r) : "f"(hi), "f"(lo)); return r;
}
static __device__ __forceinline__ uint32_t swz(uint32_t byteoff) {
    return byteoff ^ ((byteoff >> 3) & 0x70);
}
static __device__ __forceinline__ uint32_t pk4b(int a, int b, int c, int d) {
    return (uint32_t)(a & 255) | ((uint32_t)(b & 255) << 8) |
           ((uint32_t)(c & 255) << 16) | ((uint32_t)(d & 255) << 24);
}
// scaled cardinal cubic B-spline: returns round(N3(s) * QA), s in (-inf, inf)
static __device__ __forceinline__ int n3q(float s) {
    float m = fminf(s, 4.0f - s);
    m = fmaxf(m, 0.0f);
    float d = fmaxf(m - 1.0f, 0.0f);
    float v = (m * m * m - 4.0f * d * d * d) * (QA / 6.0f);
    return __float2int_rn(v);
}

// ---------------- base W packing (bf16 hi/lo) ----------------
__global__ void pack_wb(const float* __restrict__ bw) {
    int idx = blockIdx.x * 256 + threadIdx.x;   // 16 * 512 * 64
    if (idx >= 16 * OUT_F * 64) return;
    int st = idx >> 15, r = idx & 32767;
    int n = r >> 6, slot = r & 63;
    float w = bw[n * IN_F + (st & 7) * 64 + slot];
    if (st >= 8) w = w - __bfloat162float(__float2bfloat16_rn(w));
    *(__nv_bfloat16*)(g_Wb + st * 65536 + swz((unsigned)(n * 128 + slot * 2))) =
        __float2bfloat16_rn(w);
}

// ---------------- spline W quantize+pack (per-column scale) ----------------
__global__ void qpack_ws(const float* __restrict__ sw, const float* __restrict__ sc) {
    __shared__ float red[256];
    __shared__ float s_qs;
    const int n = blockIdx.x, t = threadIdx.x;
    float w[16];
    float mx = 0.0f;
#pragma unroll
    for (int p = 0; p < 2; p++) {
        int f = 2 * t + p;
        float scv = sc[n * IN_F + f];
#pragma unroll
        for (int j = 0; j < 8; j++) {
            float ww = sw[((size_t)n * IN_F + f) * 8 + j] * scv;
            w[p * 8 + j] = ww;
            mx = fmaxf(mx, fabsf(ww));
        }
    }
    red[t] = mx; __syncthreads();
    for (int o = 128; o > 0; o >>= 1) {
        if (t < o) red[t] = fmaxf(red[t], red[t + o]);
        __syncthreads();
    }
    if (t == 0) {
        float m = fmaxf(red[0], 1e-20f);
        s_qs = 127.0f / m;
        g_sWinv[n] = m / 127.0f;
    }
    __syncthreads();
    float qs = s_qs;
    uint32_t u[4];
#pragma unroll
    for (int g = 0; g < 4; g++)
        u[g] = pk4b(__float2int_rn(w[4 * g] * qs),     __float2int_rn(w[4 * g + 1] * qs),
                    __float2int_rn(w[4 * g + 2] * qs), __float2int_rn(w[4 * g + 3] * qs));
    // chunk c = t>>3 (16 feats per chunk), feat_local = (2t)&15, 8B per feat
    char* dst = g_Ws + (t >> 3) * (OUT_F * 128);
    *(uint4*)(dst + swz((unsigned)(n * 128 + ((2 * t) & 15) * 8))) = make_uint4(u[0], u[1], u[2], u[3]);
}

// ---------------- A generation ----------------
__global__ __launch_bounds__(256)
void gen_a(const float* __restrict__ x, const float* __restrict__ grid) {
    int idx = blockIdx.x * 256 + threadIdx.x;    // 16384 * 64
    int m = idx >> 6, kg = idx & 63;
    int rb = m >> 7, row = m & 127;

    const float g0 = grid[0];
    const float invh = 1.0f / (grid[1] - grid[0]);

    const float4* xp = (const float4*)(x + (size_t)m * IN_F + kg * 8);
    float4 xa = xp[0], xb = xp[1];
    float f[8] = {xa.x, xa.y, xa.z, xa.w, xb.x, xb.y, xb.z, xb.w};

    char* base = g_A + (size_t)rb * RB_BYTES;

    // silu hi / lo (bf16 chunks)
    float shi[8], slo[8];
#pragma unroll
    for (int q = 0; q < 8; q++) {
        float sv = f[q] / (1.0f + __expf(-f[q]));
        shi[q] = sv;
        slo[q] = sv - __bfloat162float(__float2bfloat16_rn(sv));
    }
    unsigned offs = swz((unsigned)(row * 128 + (kg & 7) * 16));
    *(uint4*)(base + SP_BYTES + (kg >> 3) * TILE + offs) =
        make_uint4(pk2(shi[0], shi[1]), pk2(shi[2], shi[3]), pk2(shi[4], shi[5]), pk2(shi[6], shi[7]));
    *(uint4*)(base + SP_BYTES + (8 + (kg >> 3)) * TILE + offs) =
        make_uint4(pk2(slo[0], slo[1]), pk2(slo[2], slo[3]), pk2(slo[4], slo[5]), pk2(slo[6], slo[7]));

    // spline int8 chunk kg>>1 (16 feats); this thread covers feats (kg&1)*8 .. +7
    char* sp = base + (kg >> 1) * TILE;
#pragma unroll
    for (int fp = 0; fp < 4; fp++) {       // ff pairs -> one uint4 each
        uint32_t u[4];
#pragma unroll
        for (int h = 0; h < 2; h++) {
            int ff = fp * 2 + h;
            float uu = (f[ff] - g0) * invh;
            int q0 = n3q(uu - 0.0f), q1 = n3q(uu - 1.0f), q2 = n3q(uu - 2.0f), q3 = n3q(uu - 3.0f);
            int q4 = n3q(uu - 4.0f), q5 = n3q(uu - 5.0f), q6 = n3q(uu - 6.0f), q7 = n3q(uu - 7.0f);
            u[h * 2]     = pk4b(q0, q1, q2, q3);
            u[h * 2 + 1] = pk4b(q4, q5, q6, q7);
        }
        *(uint4*)(sp + swz((unsigned)(row * 128 + (kg & 1) * 64 + fp * 16))) =
            make_uint4(u[0], u[1], u[2], u[3]);
    }
}

// ---------------- step -> global sources ----------------
static __device__ __forceinline__ const char* srcA(const char* Aglob, int s) {
    if (s < NSP) return Aglob + s * TILE;
    int t = s - NSP, kb = t / 3, r = t - 3 * kb;
    return Aglob + SP_BYTES + ((r == 1) ? (8 + kb) : kb) * TILE;
}
static __device__ __forceinline__ const char* srcB(int s, int n0) {
    if (s < NSP) return g_Ws + s * (OUT_F * 128) + (size_t)n0 * 128;
    int t = s - NSP, kb = t / 3, r = t - 3 * kb;
    return g_Wb + ((r == 2) ? (8 + kb) : kb) * 65536 + (size_t)n0 * 128;
}

// ---------------- main kernel ----------------
__global__ __launch_bounds__(256, 2)
void kan_mma(float* __restrict__ out) {
    extern __shared__ char dynraw[];
    const int tid = threadIdx.x;
    const int rb = blockIdx.y;
    const int m0 = rb * BM;
    const int n0 = blockIdx.x * BN;

    uint32_t sbase = (smem_u32(dynraw) + 1023u) & ~1023u;
    const uint32_t Abase = sbase;
    const uint32_t Bbase = sbase + 3 * TILE;

    const int l = tid & 31, wid = tid >> 5;
    const int wm = wid & 1, wn = wid >> 1;     // warp tile 64 x 32

    uint32_t offA[4], swzA[4];
#pragma unroll
    for (int mt = 0; mt < 4; mt++) {
        int rA = wm * 64 + mt * 16 + (l & 7) + (((l >> 3) & 1) << 3);
        offA[mt] = (uint32_t)(rA * 128);
        swzA[mt] = (uint32_t)((rA & 7) << 4);
    }
    const uint32_t colAsub = (uint32_t)((l >> 4) << 4);
    uint32_t offB[2], swzB[2];
#pragma unroll
    for (int nt2 = 0; nt2 < 2; nt2++) {
        int rB = wn * 32 + nt2 * 16 + (l & 7) + ((l >> 4) << 3);
        offB[nt2] = (uint32_t)(rB * 128);
        swzB[nt2] = (uint32_t)((rB & 7) << 4);
    }
    const uint32_t colBsub = (uint32_t)(((l >> 3) & 1) << 4);

    const char* Aglob = g_A + (size_t)rb * RB_BYTES;

    int   iacc[4][4][4];
    float facc[4][4][4];
#pragma unroll
    for (int a = 0; a < 4; a++)
#pragma unroll
        for (int b = 0; b < 4; b++)
#pragma unroll
            for (int c = 0; c < 4; c++) iacc[a][b][c] = 0;

    auto loadA = [&](int s, int buf) {
        const char* As = srcA(Aglob, s);
        uint32_t Ad = Abase + buf * TILE;
#pragma unroll
        for (int it = 0; it < 4; it++)
            cp16(Ad + tid * 16 + it * 4096, As + tid * 16 + it * 4096);
    };
    auto loadB = [&](int s, int buf) {
        const char* Bs = srcB(s, n0);
        uint32_t Bd = Bbase + buf * TILE;
#pragma unroll
        for (int it = 0; it < 4; it++)
            cp16(Bd + tid * 16 + it * 4096, Bs + tid * 16 + it * 4096);
    };

    loadA(0, 0); loadB(0, 0); CP_COMMIT();
    loadA(1, 1); loadB(1, 1); CP_COMMIT();

    for (int s = 0; s < NSTEP; s++) {
        CP_WAIT1();
        __syncthreads();

        const uint32_t Ab = Abase + (s % 3) * TILE;
        const uint32_t Bb = Bbase + (s % 3) * TILE;

        if (s == NSP) {
            // dequant spline s32 acc -> float, per-column scale
            float fsc[4][2];
#pragma unroll
            for (int nt = 0; nt < 4; nt++)
#pragma unroll
                for (int c2 = 0; c2 < 2; c2++)
                    fsc[nt][c2] = QAINV * g_sWinv[n0 + wn * 32 + nt * 8 + (l & 3) * 2 + c2];
#pragma unroll
            for (int mt = 0; mt < 4; mt++)
#pragma unroll
                for (int nt = 0; nt < 4; nt++) {
                    facc[mt][nt][0] = __int2float_rn(iacc[mt][nt][0]) * fsc[nt][0];
                    facc[mt][nt][1] = __int2float_rn(iacc[mt][nt][1]) * fsc[nt][1];
                    facc[mt][nt][2] = __int2float_rn(iacc[mt][nt][2]) * fsc[nt][0];
                    facc[mt][nt][3] = __int2float_rn(iacc[mt][nt][3]) * fsc[nt][1];
                }
        }

#pragma unroll
        for (int ks = 0; ks < 4; ks++) {
            uint32_t af[4][4];
#pragma unroll
            for (int mt = 0; mt < 4; mt++)
                ldsm4(af[mt], Ab + offA[mt] + ((ks * 32 + colAsub) ^ swzA[mt]));
            uint32_t bf[4][2];
#pragma unroll
            for (int nt2 = 0; nt2 < 2; nt2++) {
                uint32_t r[4];
                ldsm4(r, Bb + offB[nt2] + ((ks * 32 + colBsub) ^ swzB[nt2]));
                bf[2 * nt2][0] = r[0]; bf[2 * nt2][1] = r[1];
                bf[2 * nt2 + 1][0] = r[2]; bf[2 * nt2 + 1][1] = r[3];
            }
            if (s < NSP) {
#pragma unroll
                for (int mt = 0; mt < 4; mt++)
#pragma unroll
                    for (int nt = 0; nt < 4; nt++)
                        mma_s8(iacc[mt][nt], af[mt], bf[nt]);
            } else {
#pragma unroll
                for (int mt = 0; mt < 4; mt++)
#pragma unroll
                    for (int nt = 0; nt < 4; nt++)
                        mma_bf16(facc[mt][nt], af[mt], bf[nt]);
            }
            // overlap prefetch issue with MMA tail
            if (ks == 0 && s + 2 < NSTEP) loadA(s + 2, (s + 2) % 3);
            if (ks == 1 && s + 2 < NSTEP) loadB(s + 2, (s + 2) % 3);
        }
        CP_COMMIT();
    }

    // ---- epilogue ----
#pragma unroll
    for (int mt = 0; mt < 4; mt++) {
#pragma unroll
        for (int nt = 0; nt < 4; nt++) {
            int m = m0 + wm * 64 + mt * 16 + (l >> 2);
            int n = n0 + wn * 32 + nt * 8 + (l & 3) * 2;
            *(float2*)(out + (size_t)m * OUT_F + n) = make_float2(facc[mt][nt][0], facc[mt][nt][1]);
            *(float2*)(out + (size_t)(m + 8) * OUT_F + n) = make_float2(facc[mt][nt][2], facc[mt][nt][3]);
        }
    }
}

extern "C" void kernel_launch(void* const* d_in, const int* in_sizes, int n_in,
                              void* d_out, int out_size) {
    const float* x    = (const float*)d_in[0];
    const float* bw   = (const float*)d_in[1];
    const float* sw   = (const float*)d_in[2];
    const float* sc   = (const float*)d_in[3];
    const float* grid = (const float*)d_in[4];
    float*       out  = (float*)d_out;

    cudaFuncSetAttribute(kan_mma, cudaFuncAttributeMaxDynamicSharedMemorySize, DYN);

    pack_wb<<<(16 * OUT_F * 64 + 255) / 256, 256>>>(bw);
    qpack_ws<<<OUT_F, 256>>>(sw, sc);
    gen_a<<<(BATCH * 64) / 256, 256>>>(x, grid);

    dim3 g(OUT_F / BN, BATCH / BM);   // (4, 128) = 512 CTAs
    kan_mma<<<g, 256, DYN>>>(out);
}

// round 7
// speedup vs baseline: 2.7981x; 2.7981x over previous
#include <cuda_runtime.h>
#include <cuda_fp16.h>
#include <cstdint>

#define IN_F   512
#define OUT_F  512
#define BATCH  16384
#define BM     128
#define BN     128
#define NSTEP  72            // 8 silu chunks + 64 spline chunks, all fp16 single-pass
#define TILE   16384         // 128 rows x 128B (64 fp16 K-slots)
#define RB_BYTES (NSTEP * TILE)           // 1.125 MB per rowblock
#define DYN    (6 * TILE + 1024)          // 3 A-buf + 3 B-buf = 97 KB

__device__ char g_A[(size_t)128 * RB_BYTES];        // 144 MB augmented activations
__device__ char g_W[(size_t)NSTEP * OUT_F * 128];   // 4.7 MB packed fp16 weights

// ---------------- helpers ----------------
static __device__ __forceinline__ uint32_t smem_u32(const void* p) {
    uint32_t a;
    asm("{ .reg .u64 t; cvta.to.shared.u64 t, %1; cvt.u32.u64 %0, t; }" : "=r"(a) : "l"(p));
    return a;
}
static __device__ __forceinline__ void cp16(uint32_t dst, const void* src) {
    asm volatile("cp.async.cg.shared.global [%0], [%1], 16;" :: "r"(dst), "l"(src) : "memory");
}
#define CP_COMMIT() asm volatile("cp.async.commit_group;" ::: "memory")
#define CP_WAIT1()  asm volatile("cp.async.wait_group 1;" ::: "memory")

static __device__ __forceinline__ void ldsm4(uint32_t* r, uint32_t a) {
    asm volatile("ldmatrix.sync.aligned.m8n8.x4.shared.b16 {%0,%1,%2,%3}, [%4];"
                 : "=r"(r[0]), "=r"(r[1]), "=r"(r[2]), "=r"(r[3]) : "r"(a));
}
static __device__ __forceinline__ void mma_f16(float* d, const uint32_t* a, const uint32_t* b) {
    asm volatile("mma.sync.aligned.m16n8k16.row.col.f32.f16.f16.f32 "
                 "{%0,%1,%2,%3}, {%4,%5,%6,%7}, {%8,%9}, {%0,%1,%2,%3};"
                 : "+f"(d[0]), "+f"(d[1]), "+f"(d[2]), "+f"(d[3])
                 : "r"(a[0]), "r"(a[1]), "r"(a[2]), "r"(a[3]), "r"(b[0]), "r"(b[1]));
}
static __device__ __forceinline__ uint32_t pk2h(float lo, float hi) {   // low half = lo
    uint32_t r; asm("cvt.rn.f16x2.f32 %0, %1, %2;" : "=r"(r) : "f"(hi), "f"(lo)); return r;
}
static __device__ __forceinline__ uint32_t swz(uint32_t byteoff) {
    return byteoff ^ ((byteoff >> 3) & 0x70);
}
// cardinal cubic B-spline N3(s), support (0,4), branchless
static __device__ __forceinline__ float n3(float s) {
    float m = fmaxf(fminf(s, 4.0f - s), 0.0f);
    float d = fmaxf(m - 1.0f, 0.0f);
    return (m * m * m - 4.0f * d * d * d) * (1.0f / 6.0f);
}

// ---------------- weight packing (fp16, pre-swizzled) ----------------
// chunk st: 0..7 = base W (64 in-feats each); 8..71 = spline (8 feats x 8 bases)
__global__ void pack_w(const float* __restrict__ bw, const float* __restrict__ sw,
                       const float* __restrict__ sc) {
    int idx = blockIdx.x * 256 + threadIdx.x;     // NSTEP * 512 * 64
    if (idx >= NSTEP * OUT_F * 64) return;
    int st = idx >> 15, r = idx & 32767;
    int n = r >> 6, slot = r & 63;
    float w;
    if (st < 8) {
        w = bw[n * IN_F + st * 64 + slot];
    } else {
        int c = st - 8;
        int k = c * 8 + (slot >> 3), j = slot & 7;
        w = sw[((size_t)n * IN_F + k) * 8 + j] * sc[n * IN_F + k];
    }
    *(__half*)(g_W + (size_t)st * 65536 + swz((unsigned)(n * 128 + slot * 2))) = __float2half_rn(w);
}

// ---------------- A generation (fp16, tiled + SW128-swizzled) ----------------
__global__ __launch_bounds__(256)
void gen_a(const float* __restrict__ x, const float* __restrict__ grid) {
    int idx = blockIdx.x * 256 + threadIdx.x;    // 16384 * 64
    int m = idx >> 6, kg = idx & 63;
    int rb = m >> 7, row = m & 127;

    const float g0 = grid[0];
    const float invh = 1.0f / (grid[1] - grid[0]);

    const float4* xp = (const float4*)(x + (size_t)m * IN_F + kg * 8);
    float4 xa = xp[0], xb = xp[1];
    float f[8] = {xa.x, xa.y, xa.z, xa.w, xb.x, xb.y, xb.z, xb.w};

    char* base = g_A + (size_t)rb * RB_BYTES;

    // silu -> chunk kg>>3, slot group kg&7
    float s[8];
#pragma unroll
    for (int q = 0; q < 8; q++) s[q] = f[q] / (1.0f + __expf(-f[q]));
    *(uint4*)(base + (kg >> 3) * TILE + swz((unsigned)(row * 128 + (kg & 7) * 16))) =
        make_uint4(pk2h(s[0], s[1]), pk2h(s[2], s[3]), pk2h(s[4], s[5]), pk2h(s[6], s[7]));

    // spline chunk 8+kg: full 128B row = 8 feats x 8 bases
    char* sp = base + (8 + kg) * TILE;
#pragma unroll
    for (int fp = 0; fp < 4; fp++) {
        uint32_t u[4];
#pragma unroll
        for (int h = 0; h < 2; h++) {
            int ff = fp * 2 + h;
            float uu = (f[ff] - g0) * invh;
            u[h * 2]     = pk2h(n3(uu), n3(uu - 1.0f));
            u[h * 2 + 1] = pk2h(n3(uu - 2.0f), n3(uu - 3.0f));
            uint32_t hi0 = pk2h(n3(uu - 4.0f), n3(uu - 5.0f));
            uint32_t hi1 = pk2h(n3(uu - 6.0f), n3(uu - 7.0f));
            // place bases 0..3 then 4..7 contiguously: 8 fp16 per feature
            u[h * 2]     = u[h * 2];
            u[h * 2 + 1] = u[h * 2 + 1];
            // write second half directly below (separate 16B store per 2 feats handled via two uint4s)
            // -> assemble per-feature 16B: bases 0..7 of feature ff
            *(uint4*)(sp + swz((unsigned)(row * 128 + ff * 16))) =
                make_uint4(u[h * 2], u[h * 2 + 1], hi0, hi1);
        }
    }
}

// ---------------- main kernel: uniform streaming fp16 GEMM ----------------
__global__ __launch_bounds__(256, 2)
void kan_mma(float* __restrict__ out) {
    extern __shared__ char dynraw[];
    const int tid = threadIdx.x;
    const int rb = blockIdx.y;
    const int m0 = rb * BM;
    const int n0 = blockIdx.x * BN;

    uint32_t sbase = (smem_u32(dynraw) + 1023u) & ~1023u;
    const uint32_t Abase = sbase;
    const uint32_t Bbase = sbase + 3 * TILE;

    const int l = tid & 31, wid = tid >> 5;
    const int wm = wid & 1, wn = wid >> 1;     // warp tile 64 x 32

    uint32_t offA[4], swzA[4];
#pragma unroll
    for (int mt = 0; mt < 4; mt++) {
        int rA = wm * 64 + mt * 16 + (l & 7) + (((l >> 3) & 1) << 3);
        offA[mt] = (uint32_t)(rA * 128);
        swzA[mt] = (uint32_t)((rA & 7) << 4);
    }
    const uint32_t colAsub = (uint32_t)((l >> 4) << 4);
    uint32_t offB[2], swzB[2];
#pragma unroll
    for (int nt2 = 0; nt2 < 2; nt2++) {
        int rB = wn * 32 + nt2 * 16 + (l & 7) + ((l >> 4) << 3);
        offB[nt2] = (uint32_t)(rB * 128);
        swzB[nt2] = (uint32_t)((rB & 7) << 4);
    }
    const uint32_t colBsub = (uint32_t)(((l >> 3) & 1) << 4);

    const char* Aglob = g_A + (size_t)rb * RB_BYTES;
    const char* Bglob = g_W + (size_t)n0 * 128;

    float acc[4][4][4];
#pragma unroll
    for (int a = 0; a < 4; a++)
#pragma unroll
        for (int b = 0; b < 4; b++)
#pragma unroll
            for (int c = 0; c < 4; c++) acc[a][b][c] = 0.0f;

    auto loadAB = [&](int s, int buf) {
        const char* As = Aglob + (size_t)s * TILE;
        const char* Bs = Bglob + (size_t)s * 65536;
        uint32_t Ad = Abase + buf * TILE, Bd = Bbase + buf * TILE;
#pragma unroll
        for (int it = 0; it < 4; it++) {
            cp16(Ad + tid * 16 + it * 4096, As + tid * 16 + it * 4096);
            cp16(Bd + tid * 16 + it * 4096, Bs + tid * 16 + it * 4096);
        }
    };

    loadAB(0, 0); CP_COMMIT();
    loadAB(1, 1); CP_COMMIT();

    for (int s = 0; s < NSTEP; s++) {
        CP_WAIT1();
        __syncthreads();

        if (s + 2 < NSTEP) loadAB(s + 2, (s + 2) % 3);
        CP_COMMIT();

        const uint32_t Ab = Abase + (s % 3) * TILE;
        const uint32_t Bb = Bbase + (s % 3) * TILE;

#pragma unroll
        for (int ks = 0; ks < 4; ks++) {
            uint32_t af[4][4];
#pragma unroll
            for (int mt = 0; mt < 4; mt++)
                ldsm4(af[mt], Ab + offA[mt] + ((ks * 32 + colAsub) ^ swzA[mt]));
            uint32_t bf[4][2];
#pragma unroll
            for (int nt2 = 0; nt2 < 2; nt2++) {
                uint32_t r[4];
                ldsm4(r, Bb + offB[nt2] + ((ks * 32 + colBsub) ^ swzB[nt2]));
                bf[2 * nt2][0] = r[0]; bf[2 * nt2][1] = r[1];
                bf[2 * nt2 + 1][0] = r[2]; bf[2 * nt2 + 1][1] = r[3];
            }
#pragma unroll
            for (int mt = 0; mt < 4; mt++)
#pragma unroll
                for (int nt = 0; nt < 4; nt++)
                    mma_f16(acc[mt][nt], af[mt], bf[nt]);
        }
    }

    // ---- epilogue ----
#pragma unroll
    for (int mt = 0; mt < 4; mt++) {
#pragma unroll
        for (int nt = 0; nt < 4; nt++) {
            int m = m0 + wm * 64 + mt * 16 + (l >> 2);
            int n = n0 + wn * 32 + nt * 8 + (l & 3) * 2;
            *(float2*)(out + (size_t)m * OUT_F + n) = make_float2(acc[mt][nt][0], acc[mt][nt][1]);
            *(float2*)(out + (size_t)(m + 8) * OUT_F + n) = make_float2(acc[mt][nt][2], acc[mt][nt][3]);
        }
    }
}

extern "C" void kernel_launch(void* const* d_in, const int* in_sizes, int n_in,
                              void* d_out, int out_size) {
    const float* x    = (const float*)d_in[0];
    const float* bw   = (const float*)d_in[1];
    const float* sw   = (const float*)d_in[2];
    const float* sc   = (const float*)d_in[3];
    const float* grid = (const float*)d_in[4];
    float*       out  = (float*)d_out;

    cudaFuncSetAttribute(kan_mma, cudaFuncAttributeMaxDynamicSharedMemorySize, DYN);

    pack_w<<<(NSTEP * OUT_F * 64 + 255) / 256, 256>>>(bw, sw, sc);
    gen_a<<<(BATCH * 64) / 256, 256>>>(x, grid);

    dim3 g(OUT_F / BN, BATCH / BM);   // (4, 128) = 512 CTAs
    kan_mma<<<g, 256, DYN>>>(out);
}

// round 8
// speedup vs baseline: 3.1053x; 1.1098x over previous
#include <cuda_runtime.h>
#include <cuda_fp16.h>
#include <cstdint>

#define IN_F   512
#define OUT_F  512
#define BATCH  16384
#define BM     128
#define BN     128
#define NSTEP  72            // 8 silu chunks + 64 spline chunks, all fp16 single-pass
#define TILE   16384         // 128 rows x 128B (64 fp16 K-slots)
#define RB_BYTES (NSTEP * TILE)           // 1.125 MB per rowblock
#define DYN    (6 * TILE + 1024)          // 3 A-buf + 3 B-buf = 97 KB

#define PACK_BLOCKS (NSTEP * OUT_F * 64 / 256)   // 9216
#define GEN_BLOCKS  (BATCH * 64 / 256)           // 4096

__device__ char g_A[(size_t)128 * RB_BYTES];        // 144 MB augmented activations
__device__ char g_W[(size_t)NSTEP * OUT_F * 128];   // 4.7 MB packed fp16 weights

// ---------------- helpers ----------------
static __device__ __forceinline__ uint32_t smem_u32(const void* p) {
    uint32_t a;
    asm("{ .reg .u64 t; cvta.to.shared.u64 t, %1; cvt.u32.u64 %0, t; }" : "=r"(a) : "l"(p));
    return a;
}
static __device__ __forceinline__ void cp16(uint32_t dst, const void* src) {
    asm volatile("cp.async.cg.shared.global [%0], [%1], 16;" :: "r"(dst), "l"(src) : "memory");
}
#define CP_COMMIT() asm volatile("cp.async.commit_group;" ::: "memory")
#define CP_WAIT1()  asm volatile("cp.async.wait_group 1;" ::: "memory")

static __device__ __forceinline__ void ldsm4(uint32_t* r, uint32_t a) {
    asm volatile("ldmatrix.sync.aligned.m8n8.x4.shared.b16 {%0,%1,%2,%3}, [%4];"
                 : "=r"(r[0]), "=r"(r[1]), "=r"(r[2]), "=r"(r[3]) : "r"(a));
}
static __device__ __forceinline__ void mma_f16(float* d, const uint32_t* a, const uint32_t* b) {
    asm volatile("mma.sync.aligned.m16n8k16.row.col.f32.f16.f16.f32 "
                 "{%0,%1,%2,%3}, {%4,%5,%6,%7}, {%8,%9}, {%0,%1,%2,%3};"
                 : "+f"(d[0]), "+f"(d[1]), "+f"(d[2]), "+f"(d[3])
                 : "r"(a[0]), "r"(a[1]), "r"(a[2]), "r"(a[3]), "r"(b[0]), "r"(b[1]));
}
static __device__ __forceinline__ uint32_t pk2h(float lo, float hi) {   // low half = lo
    uint32_t r; asm("cvt.rn.f16x2.f32 %0, %1, %2;" : "=r"(r) : "f"(hi), "f"(lo)); return r;
}
static __device__ __forceinline__ uint32_t swz(uint32_t byteoff) {
    return byteoff ^ ((byteoff >> 3) & 0x70);
}
// cardinal cubic B-spline N3(s), support (0,4), branchless
static __device__ __forceinline__ float n3(float s) {
    float m = fmaxf(fminf(s, 4.0f - s), 0.0f);
    float d = fmaxf(m - 1.0f, 0.0f);
    return (m * m * m - 4.0f * d * d * d) * (1.0f / 6.0f);
}

// ---------------- fused prep: pack W (blocks [0,PACK)) + gen A (rest) ----------------
__global__ __launch_bounds__(256)
void prep(const float* __restrict__ bw, const float* __restrict__ sw,
          const float* __restrict__ sc, const float* __restrict__ x,
          const float* __restrict__ grid) {
    if (blockIdx.x < PACK_BLOCKS) {
        // chunk st: 0..7 = base W (64 in-feats each); 8..71 = spline (8 feats x 8 bases)
        int idx = blockIdx.x * 256 + threadIdx.x;
        int st = idx >> 15, r = idx & 32767;
        int n = r >> 6, slot = r & 63;
        float w;
        if (st < 8) {
            w = bw[n * IN_F + st * 64 + slot];
        } else {
            int c = st - 8;
            int k = c * 8 + (slot >> 3), j = slot & 7;
            w = sw[((size_t)n * IN_F + k) * 8 + j] * sc[n * IN_F + k];
        }
        *(__half*)(g_W + (size_t)st * 65536 + swz((unsigned)(n * 128 + slot * 2))) =
            __float2half_rn(w);
        return;
    }

    int idx = (blockIdx.x - PACK_BLOCKS) * 256 + threadIdx.x;   // 16384 * 64
    int m = idx >> 6, kg = idx & 63;
    int rb = m >> 7, row = m & 127;

    const float g0 = grid[0];
    const float invh = 1.0f / (grid[1] - grid[0]);

    const float4* xp = (const float4*)(x + (size_t)m * IN_F + kg * 8);
    float4 xa = xp[0], xb = xp[1];
    float f[8] = {xa.x, xa.y, xa.z, xa.w, xb.x, xb.y, xb.z, xb.w};

    char* base = g_A + (size_t)rb * RB_BYTES;

    // silu -> chunk kg>>3, slot group kg&7
    float s[8];
#pragma unroll
    for (int q = 0; q < 8; q++) s[q] = f[q] / (1.0f + __expf(-f[q]));
    *(uint4*)(base + (kg >> 3) * TILE + swz((unsigned)(row * 128 + (kg & 7) * 16))) =
        make_uint4(pk2h(s[0], s[1]), pk2h(s[2], s[3]), pk2h(s[4], s[5]), pk2h(s[6], s[7]));

    // spline chunk 8+kg: full 128B row = 8 feats x 8 bases (16B per feature)
    char* sp = base + (8 + kg) * TILE;
#pragma unroll
    for (int ff = 0; ff < 8; ff++) {
        float uu = (f[ff] - g0) * invh;
        uint4 v = make_uint4(pk2h(n3(uu), n3(uu - 1.0f)),
                             pk2h(n3(uu - 2.0f), n3(uu - 3.0f)),
                             pk2h(n3(uu - 4.0f), n3(uu - 5.0f)),
                             pk2h(n3(uu - 6.0f), n3(uu - 7.0f)));
        *(uint4*)(sp + swz((unsigned)(row * 128 + ff * 16))) = v;
    }
}

// ---------------- main kernel: uniform streaming fp16 GEMM ----------------
__global__ __launch_bounds__(256, 2)
void kan_mma(float* __restrict__ out) {
    extern __shared__ char dynraw[];
    const int tid = threadIdx.x;
    const int rb = blockIdx.y;
    const int m0 = rb * BM;
    const int n0 = blockIdx.x * BN;

    uint32_t sbase = (smem_u32(dynraw) + 1023u) & ~1023u;
    const uint32_t A0 = sbase,          A1 = sbase + TILE,     A2 = sbase + 2 * TILE;
    const uint32_t B0 = sbase + 3*TILE, B1 = sbase + 4 * TILE, B2 = sbase + 5 * TILE;

    const int l = tid & 31, wid = tid >> 5;
    const int wm = wid & 1, wn = wid >> 1;     // warp tile 64 x 32

    uint32_t offA[4], swzA[4];
#pragma unroll
    for (int mt = 0; mt < 4; mt++) {
        int rA = wm * 64 + mt * 16 + (l & 7) + (((l >> 3) & 1) << 3);
        offA[mt] = (uint32_t)(rA * 128);
        swzA[mt] = (uint32_t)((rA & 7) << 4);
    }
    const uint32_t colAsub = (uint32_t)((l >> 4) << 4);
    uint32_t offB[2], swzB[2];
#pragma unroll
    for (int nt2 = 0; nt2 < 2; nt2++) {
        int rB = wn * 32 + nt2 * 16 + (l & 7) + ((l >> 4) << 3);
        offB[nt2] = (uint32_t)(rB * 128);
        swzB[nt2] = (uint32_t)((rB & 7) << 4);
    }
    const uint32_t colBsub = (uint32_t)(((l >> 3) & 1) << 4);

    const char* Aglob = g_A + (size_t)rb * RB_BYTES;
    const char* Bglob = g_W + (size_t)n0 * 128;

    float acc[4][4][4];
#pragma unroll
    for (int a = 0; a < 4; a++)
#pragma unroll
        for (int b = 0; b < 4; b++)
#pragma unroll
            for (int c = 0; c < 4; c++) acc[a][b][c] = 0.0f;

    const uint32_t t16 = (uint32_t)(tid * 16);

    // one full pipeline step; prefetch for s+2 interleaved into the MMA body
    auto step = [&](int s, uint32_t Ab, uint32_t Bb, uint32_t Ad2, uint32_t Bd2) {
        CP_WAIT1();
        __syncthreads();

        const bool pf = (s + 2 < NSTEP);
        const char* As2 = Aglob + (size_t)(s + 2) * TILE;
        const char* Bs2 = Bglob + (size_t)(s + 2) * 65536;

#pragma unroll
        for (int ks = 0; ks < 4; ks++) {
            uint32_t af[4][4];
#pragma unroll
            for (int mt = 0; mt < 4; mt++)
                ldsm4(af[mt], Ab + offA[mt] + ((ks * 32 + colAsub) ^ swzA[mt]));
            uint32_t bf[4][2];
#pragma unroll
            for (int nt2 = 0; nt2 < 2; nt2++) {
                uint32_t r[4];
                ldsm4(r, Bb + offB[nt2] + ((ks * 32 + colBsub) ^ swzB[nt2]));
                bf[2 * nt2][0] = r[0]; bf[2 * nt2][1] = r[1];
                bf[2 * nt2 + 1][0] = r[2]; bf[2 * nt2 + 1][1] = r[3];
            }
#pragma unroll
            for (int mt = 0; mt < 4; mt++)
#pragma unroll
                for (int nt = 0; nt < 4; nt++)
                    mma_f16(acc[mt][nt], af[mt], bf[nt]);

            if (ks == 0 && pf) {
#pragma unroll
                for (int it = 0; it < 4; it++)
                    cp16(Ad2 + t16 + it * 4096, As2 + t16 + it * 4096);
            }
            if (ks == 1 && pf) {
#pragma unroll
                for (int it = 0; it < 4; it++)
                    cp16(Bd2 + t16 + it * 4096, Bs2 + t16 + it * 4096);
            }
        }
        CP_COMMIT();
    };

    // prologue: load steps 0, 1
    {
        const char* As = Aglob;
        const char* Bs = Bglob;
#pragma unroll
        for (int it = 0; it < 4; it++) {
            cp16(A0 + t16 + it * 4096, As + t16 + it * 4096);
            cp16(B0 + t16 + it * 4096, Bs + t16 + it * 4096);
        }
        CP_COMMIT();
        As += TILE; Bs += 65536;
#pragma unroll
        for (int it = 0; it < 4; it++) {
            cp16(A1 + t16 + it * 4096, As + t16 + it * 4096);
            cp16(B1 + t16 + it * 4096, Bs + t16 + it * 4096);
        }
        CP_COMMIT();
    }

    for (int s = 0; s < NSTEP; s += 3) {
        step(s,     A0, B0, A2, B2);
        step(s + 1, A1, B1, A0, B0);
        step(s + 2, A2, B2, A1, B1);
    }

    // ---- epilogue ----
#pragma unroll
    for (int mt = 0; mt < 4; mt++) {
#pragma unroll
        for (int nt = 0; nt < 4; nt++) {
            int m = m0 + wm * 64 + mt * 16 + (l >> 2);
            int n = n0 + wn * 32 + nt * 8 + (l & 3) * 2;
            *(float2*)(out + (size_t)m * OUT_F + n) = make_float2(acc[mt][nt][0], acc[mt][nt][1]);
            *(float2*)(out + (size_t)(m + 8) * OUT_F + n) = make_float2(acc[mt][nt][2], acc[mt][nt][3]);
        }
    }
}

extern "C" void kernel_launch(void* const* d_in, const int* in_sizes, int n_in,
                              void* d_out, int out_size) {
    const float* x    = (const float*)d_in[0];
    const float* bw   = (const float*)d_in[1];
    const float* sw   = (const float*)d_in[2];
    const float* sc   = (const float*)d_in[3];
    const float* grid = (const float*)d_in[4];
    float*       out  = (float*)d_out;

    cudaFuncSetAttribute(kan_mma, cudaFuncAttributeMaxDynamicSharedMemorySize, DYN);

    prep<<<PACK_BLOCKS + GEN_BLOCKS, 256>>>(bw, sw, sc, x, grid);

    dim3 g(OUT_F / BN, BATCH / BM);   // (4, 128) = 512 CTAs
    kan_mma<<<g, 256, DYN>>>(out);
}

// round 9
// speedup vs baseline: 3.5634x; 1.1475x over previous
#include <cuda_runtime.h>
#include <cuda_fp16.h>
#include <cstdint>

#define IN_F   512
#define OUT_F  512
#define BATCH  16384
#define BM     128
#define BN     128
#define NSTEP  72            // 8 silu chunks + 64 spline chunks, all fp16 single-pass
#define TILE   16384         // 128 rows x 128B (64 fp16 K-slots)
#define RB_BYTES (NSTEP * TILE)           // 1.125 MB per rowblock
#define DYN    (6 * TILE + 1024)          // 3 A-buf + 3 B-buf = 97 KB

#define PACK_BLOCKS   (NSTEP * OUT_F * 64 / 256)   // 9216
#define SILU_BLOCKS   (BATCH * 64 / 256)           // 4096
#define SPLINE_BLOCKS (BATCH * IN_F / 256)         // 32768

__device__ char g_A[(size_t)128 * RB_BYTES];        // 144 MB augmented activations
__device__ char g_W[(size_t)NSTEP * OUT_F * 128];   // 4.7 MB packed fp16 weights

// ---------------- helpers ----------------
static __device__ __forceinline__ uint32_t smem_u32(const void* p) {
    uint32_t a;
    asm("{ .reg .u64 t; cvta.to.shared.u64 t, %1; cvt.u32.u64 %0, t; }" : "=r"(a) : "l"(p));
    return a;
}
static __device__ __forceinline__ void cp16(uint32_t dst, const void* src) {
    asm volatile("cp.async.cg.shared.global [%0], [%1], 16;" :: "r"(dst), "l"(src) : "memory");
}
#define CP_COMMIT() asm volatile("cp.async.commit_group;" ::: "memory")
#define CP_WAIT1()  asm volatile("cp.async.wait_group 1;" ::: "memory")

static __device__ __forceinline__ void ldsm4(uint32_t* r, uint32_t a) {
    asm volatile("ldmatrix.sync.aligned.m8n8.x4.shared.b16 {%0,%1,%2,%3}, [%4];"
                 : "=r"(r[0]), "=r"(r[1]), "=r"(r[2]), "=r"(r[3]) : "r"(a));
}
static __device__ __forceinline__ void mma_f16(float* d, const uint32_t* a, const uint32_t* b) {
    asm volatile("mma.sync.aligned.m16n8k16.row.col.f32.f16.f16.f32 "
                 "{%0,%1,%2,%3}, {%4,%5,%6,%7}, {%8,%9}, {%0,%1,%2,%3};"
                 : "+f"(d[0]), "+f"(d[1]), "+f"(d[2]), "+f"(d[3])
                 : "r"(a[0]), "r"(a[1]), "r"(a[2]), "r"(a[3]), "r"(b[0]), "r"(b[1]));
}
static __device__ __forceinline__ uint32_t pk2h(float lo, float hi) {   // low half = lo
    uint32_t r; asm("cvt.rn.f16x2.f32 %0, %1, %2;" : "=r"(r) : "f"(hi), "f"(lo)); return r;
}
static __device__ __forceinline__ uint32_t swz(uint32_t byteoff) {
    return byteoff ^ ((byteoff >> 3) & 0x70);
}
// cardinal cubic B-spline N3(s), support (0,4), branchless
static __device__ __forceinline__ float n3(float s) {
    float m = fmaxf(fminf(s, 4.0f - s), 0.0f);
    float d = fmaxf(m - 1.0f, 0.0f);
    return (m * m * m - 4.0f * d * d * d) * (1.0f / 6.0f);
}

// ---------------- fused prep ----------------
// blocks [0, PACK)                : pack weights (fp16, pre-swizzled)
// blocks [PACK, PACK+SILU)        : silu chunks 0..7
// blocks [PACK+SILU, ...+SPLINE)  : spline chunks 8..71, store-coalesced
__global__ __launch_bounds__(256)
void prep(const float* __restrict__ bw, const float* __restrict__ sw,
          const float* __restrict__ sc, const float* __restrict__ x,
          const float* __restrict__ grid) {
    if (blockIdx.x < PACK_BLOCKS) {
        int idx = blockIdx.x * 256 + threadIdx.x;
        int st = idx >> 15, r = idx & 32767;
        int n = r >> 6, slot = r & 63;
        float w;
        if (st < 8) {
            w = bw[n * IN_F + st * 64 + slot];
        } else {
            int c = st - 8;
            int k = c * 8 + (slot >> 3), j = slot & 7;
            w = sw[((size_t)n * IN_F + k) * 8 + j] * sc[n * IN_F + k];
        }
        *(__half*)(g_W + (size_t)st * 65536 + swz((unsigned)(n * 128 + slot * 2))) =
            __float2half_rn(w);
        return;
    }

    if (blockIdx.x < PACK_BLOCKS + SILU_BLOCKS) {
        // silu: thread -> (row m, slot-group kg): 8 features, one 16B store
        int idx = (blockIdx.x - PACK_BLOCKS) * 256 + threadIdx.x;   // 16384 * 64
        int m = idx >> 6, kg = idx & 63;
        int rb = m >> 7, row = m & 127;
        const float4* xp = (const float4*)(x + (size_t)m * IN_F + kg * 8);
        float4 xa = xp[0], xb = xp[1];
        float f[8] = {xa.x, xa.y, xa.z, xa.w, xb.x, xb.y, xb.z, xb.w};
        float s[8];
#pragma unroll
        for (int q = 0; q < 8; q++) s[q] = f[q] / (1.0f + __expf(-f[q]));
        *(uint4*)(g_A + (size_t)rb * RB_BYTES + (kg >> 3) * TILE +
                  swz((unsigned)(row * 128 + (kg & 7) * 16))) =
            make_uint4(pk2h(s[0], s[1]), pk2h(s[2], s[3]), pk2h(s[4], s[5]), pk2h(s[6], s[7]));
        return;
    }

    // spline: warp -> (chunk c, 4 consecutive rows); lane -> (row, one feature)
    // store per warp = 4 x 128B contiguous (fully coalesced)
    int idx = (blockIdx.x - PACK_BLOCKS - SILU_BLOCKS) * 256 + threadIdx.x;  // 16384*512
    int w = idx >> 5, l = idx & 31;
    int c = w & 63, rg = w >> 6;                  // chunk, row-group
    int m = rg * 4 + (l >> 3);                    // global row
    int ff = l & 7;                               // feature within chunk
    int rb = m >> 7, row = m & 127;

    const float g0 = grid[0];
    const float invh = 1.0f / (grid[1] - grid[0]);

    float xv = x[(size_t)m * IN_F + c * 8 + ff];
    float uu = (xv - g0) * invh;
    uint4 v = make_uint4(pk2h(n3(uu),        n3(uu - 1.0f)),
                         pk2h(n3(uu - 2.0f), n3(uu - 3.0f)),
                         pk2h(n3(uu - 4.0f), n3(uu - 5.0f)),
                         pk2h(n3(uu - 6.0f), n3(uu - 7.0f)));
    *(uint4*)(g_A + (size_t)rb * RB_BYTES + (8 + c) * TILE +
              swz((unsigned)(row * 128 + ff * 16))) = v;
}

// ---------------- main kernel: uniform streaming fp16 GEMM ----------------
__global__ __launch_bounds__(256, 2)
void kan_mma(float* __restrict__ out) {
    extern __shared__ char dynraw[];
    const int tid = threadIdx.x;
    const int rb = blockIdx.y;
    const int m0 = rb * BM;
    const int n0 = blockIdx.x * BN;

    uint32_t sbase = (smem_u32(dynraw) + 1023u) & ~1023u;
    const uint32_t A0 = sbase,          A1 = sbase + TILE,     A2 = sbase + 2 * TILE;
    const uint32_t B0 = sbase + 3*TILE, B1 = sbase + 4 * TILE, B2 = sbase + 5 * TILE;

    const int l = tid & 31, wid = tid >> 5;
    const int wm = wid & 1, wn = wid >> 1;     // warp tile 64 x 32

    uint32_t offA[4], swzA[4];
#pragma unroll
    for (int mt = 0; mt < 4; mt++) {
        int rA = wm * 64 + mt * 16 + (l & 7) + (((l >> 3) & 1) << 3);
        offA[mt] = (uint32_t)(rA * 128);
        swzA[mt] = (uint32_t)((rA & 7) << 4);
    }
    const uint32_t colAsub = (uint32_t)((l >> 4) << 4);
    uint32_t offB[2], swzB[2];
#pragma unroll
    for (int nt2 = 0; nt2 < 2; nt2++) {
        int rB = wn * 32 + nt2 * 16 + (l & 7) + ((l >> 4) << 3);
        offB[nt2] = (uint32_t)(rB * 128);
        swzB[nt2] = (uint32_t)((rB & 7) << 4);
    }
    const uint32_t colBsub = (uint32_t)(((l >> 3) & 1) << 4);

    const char* Aglob = g_A + (size_t)rb * RB_BYTES;
    const char* Bglob = g_W + (size_t)n0 * 128;

    float acc[4][4][4];
#pragma unroll
    for (int a = 0; a < 4; a++)
#pragma unroll
        for (int b = 0; b < 4; b++)
#pragma unroll
            for (int c = 0; c < 4; c++) acc[a][b][c] = 0.0f;

    const uint32_t t16 = (uint32_t)(tid * 16);

    auto step = [&](int s, uint32_t Ab, uint32_t Bb, uint32_t Ad2, uint32_t Bd2) {
        CP_WAIT1();
        __syncthreads();

        const bool pf = (s + 2 < NSTEP);
        const char* As2 = Aglob + (size_t)(s + 2) * TILE;
        const char* Bs2 = Bglob + (size_t)(s + 2) * 65536;

#pragma unroll
        for (int ks = 0; ks < 4; ks++) {
            uint32_t af[4][4];
#pragma unroll
            for (int mt = 0; mt < 4; mt++)
                ldsm4(af[mt], Ab + offA[mt] + ((ks * 32 + colAsub) ^ swzA[mt]));
            uint32_t bf[4][2];
#pragma unroll
            for (int nt2 = 0; nt2 < 2; nt2++) {
                uint32_t r[4];
                ldsm4(r, Bb + offB[nt2] + ((ks * 32 + colBsub) ^ swzB[nt2]));
                bf[2 * nt2][0] = r[0]; bf[2 * nt2][1] = r[1];
                bf[2 * nt2 + 1][0] = r[2]; bf[2 * nt2 + 1][1] = r[3];
            }
#pragma unroll
            for (int mt = 0; mt < 4; mt++)
#pragma unroll
                for (int nt = 0; nt < 4; nt++)
                    mma_f16(acc[mt][nt], af[mt], bf[nt]);

            if (ks == 0 && pf) {
#pragma unroll
                for (int it = 0; it < 4; it++)
                    cp16(Ad2 + t16 + it * 4096, As2 + t16 + it * 4096);
            }
            if (ks == 1 && pf) {
#pragma unroll
                for (int it = 0; it < 4; it++)
                    cp16(Bd2 + t16 + it * 4096, Bs2 + t16 + it * 4096);
            }
        }
        CP_COMMIT();
    };

    // prologue: load steps 0, 1
    {
        const char* As = Aglob;
        const char* Bs = Bglob;
#pragma unroll
        for (int it = 0; it < 4; it++) {
            cp16(A0 + t16 + it * 4096, As + t16 + it * 4096);
            cp16(B0 + t16 + it * 4096, Bs + t16 + it * 4096);
        }
        CP_COMMIT();
        As += TILE; Bs += 65536;
#pragma unroll
        for (int it = 0; it < 4; it++) {
            cp16(A1 + t16 + it * 4096, As + t16 + it * 4096);
            cp16(B1 + t16 + it * 4096, Bs + t16 + it * 4096);
        }
        CP_COMMIT();
    }

    for (int s = 0; s < NSTEP; s += 3) {
        step(s,     A0, B0, A2, B2);
        step(s + 1, A1, B1, A0, B0);
        step(s + 2, A2, B2, A1, B1);
    }

    // ---- epilogue ----
#pragma unroll
    for (int mt = 0; mt < 4; mt++) {
#pragma unroll
        for (int nt = 0; nt < 4; nt++) {
            int m = m0 + wm * 64 + mt * 16 + (l >> 2);
            int n = n0 + wn * 32 + nt * 8 + (l & 3) * 2;
            *(float2*)(out + (size_t)m * OUT_F + n) = make_float2(acc[mt][nt][0], acc[mt][nt][1]);
            *(float2*)(out + (size_t)(m + 8) * OUT_F + n) = make_float2(acc[mt][nt][2], acc[mt][nt][3]);
        }
    }
}

extern "C" void kernel_launch(void* const* d_in, const int* in_sizes, int n_in,
                              void* d_out, int out_size) {
    const float* x    = (const float*)d_in[0];
    const float* bw   = (const float*)d_in[1];
    const float* sw   = (const float*)d_in[2];
    const float* sc   = (const float*)d_in[3];
    const float* grid = (const float*)d_in[4];
    float*       out  = (float*)d_out;

    cudaFuncSetAttribute(kan_mma, cudaFuncAttributeMaxDynamicSharedMemorySize, DYN);

    prep<<<PACK_BLOCKS + SILU_BLOCKS + SPLINE_BLOCKS, 256>>>(bw, sw, sc, x, grid);

    dim3 g(OUT_F / BN, BATCH / BM);   // (4, 128) = 512 CTAs
    kan_mma<<<g, 256, DYN>>>(out);
}

// round 10
// speedup vs baseline: 3.5775x; 1.0039x over previous
#include <cuda_runtime.h>
#include <cuda_fp16.h>
#include <cstdint>

#define IN_F   512
#define OUT_F  512
#define BATCH  16384
#define BM     128
#define BN     128
#define NSTEP  72            // 8 silu chunks + 64 spline chunks, all fp16 single-pass
#define TILE   16384         // 128 rows x 128B (64 fp16 K-slots)
#define RB_BYTES (NSTEP * TILE)           // 1.125 MB per rowblock
#define DYN    (6 * TILE + 1024)          // 3 A-buf + 3 B-buf = 97 KB

#define PACK_BLOCKS   (NSTEP * OUT_F * 64 / 256)   // 9216
#define SILU_BLOCKS   (BATCH * 64 / 256)           // 4096
#define SPLINE_BLOCKS (BATCH * IN_F / 256)         // 32768

__device__ char g_A[(size_t)128 * RB_BYTES];        // 144 MB augmented activations
__device__ char g_W[(size_t)NSTEP * OUT_F * 128];   // 4.7 MB packed fp16 weights

// ---------------- helpers ----------------
static __device__ __forceinline__ uint32_t smem_u32(const void* p) {
    uint32_t a;
    asm("{ .reg .u64 t; cvta.to.shared.u64 t, %1; cvt.u32.u64 %0, t; }" : "=r"(a) : "l"(p));
    return a;
}
static __device__ __forceinline__ void cp16(uint32_t dst, const void* src) {
    asm volatile("cp.async.cg.shared.global [%0], [%1], 16;" :: "r"(dst), "l"(src) : "memory");
}
#define CP_COMMIT() asm volatile("cp.async.commit_group;" ::: "memory")
#define CP_WAIT1()  asm volatile("cp.async.wait_group 1;" ::: "memory")

static __device__ __forceinline__ void ldsm4(uint32_t* r, uint32_t a) {
    asm volatile("ldmatrix.sync.aligned.m8n8.x4.shared.b16 {%0,%1,%2,%3}, [%4];"
                 : "=r"(r[0]), "=r"(r[1]), "=r"(r[2]), "=r"(r[3]) : "r"(a));
}
static __device__ __forceinline__ void mma_f16(float* d, const uint32_t* a, const uint32_t* b) {
    asm volatile("mma.sync.aligned.m16n8k16.row.col.f32.f16.f16.f32 "
                 "{%0,%1,%2,%3}, {%4,%5,%6,%7}, {%8,%9}, {%0,%1,%2,%3};"
                 : "+f"(d[0]), "+f"(d[1]), "+f"(d[2]), "+f"(d[3])
                 : "r"(a[0]), "r"(a[1]), "r"(a[2]), "r"(a[3]), "r"(b[0]), "r"(b[1]));
}
static __device__ __forceinline__ uint32_t pk2h(float lo, float hi) {   // low half = lo
    uint32_t r; asm("cvt.rn.f16x2.f32 %0, %1, %2;" : "=r"(r) : "f"(hi), "f"(lo)); return r;
}
static __device__ __forceinline__ uint32_t swz(uint32_t byteoff) {
    return byteoff ^ ((byteoff >> 3) & 0x70);
}
// silu via single-MUFU tanh approx: silu(x) = 0.5x * (1 + tanh(x/2))
static __device__ __forceinline__ float silu_fast(float x) {
    float th;
    asm("tanh.approx.f32 %0, %1;" : "=f"(th) : "f"(0.5f * x));
    float hx = 0.5f * x;
    return fmaf(hx, th, hx);
}
// cardinal cubic B-spline N3(s), support (0,4), branchless
static __device__ __forceinline__ float n3(float s) {
    float m = fmaxf(fminf(s, 4.0f - s), 0.0f);
    float d = fmaxf(m - 1.0f, 0.0f);
    return (m * m * m - 4.0f * d * d * d) * (1.0f / 6.0f);
}

// ---------------- fused prep ----------------
// blocks [0, PACK)                : pack weights (fp16, pre-swizzled)
// blocks [PACK, PACK+SILU)        : silu chunks 0..7
// blocks [PACK+SILU, ...+SPLINE)  : spline chunks 8..71, store-coalesced
__global__ __launch_bounds__(256)
void prep(const float* __restrict__ bw, const float* __restrict__ sw,
          const float* __restrict__ sc, const float* __restrict__ x,
          const float* __restrict__ grid) {
    if (blockIdx.x < PACK_BLOCKS) {
        int idx = blockIdx.x * 256 + threadIdx.x;
        int st = idx >> 15, r = idx & 32767;
        int n = r >> 6, slot = r & 63;
        float w;
        if (st < 8) {
            w = bw[n * IN_F + st * 64 + slot];
        } else {
            int c = st - 8;
            int k = c * 8 + (slot >> 3), j = slot & 7;
            w = sw[((size_t)n * IN_F + k) * 8 + j] * sc[n * IN_F + k];
        }
        *(__half*)(g_W + (size_t)st * 65536 + swz((unsigned)(n * 128 + slot * 2))) =
            __float2half_rn(w);
        return;
    }

    if (blockIdx.x < PACK_BLOCKS + SILU_BLOCKS) {
        // silu: thread -> (row m, slot-group kg): 8 features, one 16B store
        int idx = (blockIdx.x - PACK_BLOCKS) * 256 + threadIdx.x;   // 16384 * 64
        int m = idx >> 6, kg = idx & 63;
        int rb = m >> 7, row = m & 127;
        const float4* xp = (const float4*)(x + (size_t)m * IN_F + kg * 8);
        float4 xa = xp[0], xb = xp[1];
        float f[8] = {xa.x, xa.y, xa.z, xa.w, xb.x, xb.y, xb.z, xb.w};
        float s[8];
#pragma unroll
        for (int q = 0; q < 8; q++) s[q] = silu_fast(f[q]);
        *(uint4*)(g_A + (size_t)rb * RB_BYTES + (kg >> 3) * TILE +
                  swz((unsigned)(row * 128 + (kg & 7) * 16))) =
            make_uint4(pk2h(s[0], s[1]), pk2h(s[2], s[3]), pk2h(s[4], s[5]), pk2h(s[6], s[7]));
        return;
    }

    // spline: warp -> (chunk c, 4 consecutive rows); lane -> (row, one feature)
    // store per warp = 4 x 128B contiguous (fully coalesced)
    int idx = (blockIdx.x - PACK_BLOCKS - SILU_BLOCKS) * 256 + threadIdx.x;  // 16384*512
    int w = idx >> 5, l = idx & 31;
    int c = w & 63, rg = w >> 6;                  // chunk, row-group
    int m = rg * 4 + (l >> 3);                    // global row
    int ff = l & 7;                               // feature within chunk
    int rb = m >> 7, row = m & 127;

    const float g0 = grid[0];
    const float invh = 1.0f / (grid[1] - grid[0]);

    float xv = x[(size_t)m * IN_F + c * 8 + ff];
    float uu = (xv - g0) * invh;
    uint4 v = make_uint4(pk2h(n3(uu),        n3(uu - 1.0f)),
                         pk2h(n3(uu - 2.0f), n3(uu - 3.0f)),
                         pk2h(n3(uu - 4.0f), n3(uu - 5.0f)),
                         pk2h(n3(uu - 6.0f), n3(uu - 7.0f)));
    *(uint4*)(g_A + (size_t)rb * RB_BYTES + (8 + c) * TILE +
              swz((unsigned)(row * 128 + ff * 16))) = v;
}

// ---------------- main kernel: uniform streaming fp16 GEMM ----------------
__global__ __launch_bounds__(256, 2)
void kan_mma(float* __restrict__ out) {
    extern __shared__ char dynraw[];
    const int tid = threadIdx.x;
    const int rb = blockIdx.y;
    const int m0 = rb * BM;
    const int n0 = blockIdx.x * BN;

    uint32_t sbase = (smem_u32(dynraw) + 1023u) & ~1023u;
    const uint32_t A0 = sbase,          A1 = sbase + TILE,     A2 = sbase + 2 * TILE;
    const uint32_t B0 = sbase + 3*TILE, B1 = sbase + 4 * TILE, B2 = sbase + 5 * TILE;

    const int l = tid & 31, wid = tid >> 5;
    const int wm = wid & 1, wn = wid >> 1;     // warp tile 64 x 32

    uint32_t offA[4], swzA[4];
#pragma unroll
    for (int mt = 0; mt < 4; mt++) {
        int rA = wm * 64 + mt * 16 + (l & 7) + (((l >> 3) & 1) << 3);
        offA[mt] = (uint32_t)(rA * 128);
        swzA[mt] = (uint32_t)((rA & 7) << 4);
    }
    const uint32_t colAsub = (uint32_t)((l >> 4) << 4);
    uint32_t offB[2], swzB[2];
#pragma unroll
    for (int nt2 = 0; nt2 < 2; nt2++) {
        int rB = wn * 32 + nt2 * 16 + (l & 7) + ((l >> 4) << 3);
        offB[nt2] = (uint32_t)(rB * 128);
        swzB[nt2] = (uint32_t)((rB & 7) << 4);
    }
    const uint32_t colBsub = (uint32_t)(((l >> 3) & 1) << 4);

    const char* Aglob = g_A + (size_t)rb * RB_BYTES;
    const char* Bglob = g_W + (size_t)n0 * 128;

    float acc[4][4][4];
#pragma unroll
    for (int a = 0; a < 4; a++)
#pragma unroll
        for (int b = 0; b < 4; b++)
#pragma unroll
            for (int c = 0; c < 4; c++) acc[a][b][c] = 0.0f;

    const uint32_t t16 = (uint32_t)(tid * 16);

    auto step = [&](int s, uint32_t Ab, uint32_t Bb, uint32_t Ad2, uint32_t Bd2) {
        CP_WAIT1();
        __syncthreads();

        const bool pf = (s + 2 < NSTEP);
        const char* As2 = Aglob + (size_t)(s + 2) * TILE;
        const char* Bs2 = Bglob + (size_t)(s + 2) * 65536;

#pragma unroll
        for (int ks = 0; ks < 4; ks++) {
            uint32_t af[4][4];
#pragma unroll
            for (int mt = 0; mt < 4; mt++)
                ldsm4(af[mt], Ab + offA[mt] + ((ks * 32 + colAsub) ^ swzA[mt]));
            uint32_t bf[4][2];
#pragma unroll
            for (int nt2 = 0; nt2 < 2; nt2++) {
                uint32_t r[4];
                ldsm4(r, Bb + offB[nt2] + ((ks * 32 + colBsub) ^ swzB[nt2]));
                bf[2 * nt2][0] = r[0]; bf[2 * nt2][1] = r[1];
                bf[2 * nt2 + 1][0] = r[2]; bf[2 * nt2 + 1][1] = r[3];
            }
#pragma unroll
            for (int mt = 0; mt < 4; mt++)
#pragma unroll
                for (int nt = 0; nt < 4; nt++)
                    mma_f16(acc[mt][nt], af[mt], bf[nt]);

            if (ks == 0 && pf) {
#pragma unroll
                for (int it = 0; it < 4; it++)
                    cp16(Ad2 + t16 + it * 4096, As2 + t16 + it * 4096);
            }
            if (ks == 1 && pf) {
#pragma unroll
                for (int it = 0; it < 4; it++)
                    cp16(Bd2 + t16 + it * 4096, Bs2 + t16 + it * 4096);
            }
        }
        CP_COMMIT();
    };

    // prologue: load steps 0, 1
    {
        const char* As = Aglob;
        const char* Bs = Bglob;
#pragma unroll
        for (int it = 0; it < 4; it++) {
            cp16(A0 + t16 + it * 4096, As + t16 + it * 4096);
            cp16(B0 + t16 + it * 4096, Bs + t16 + it * 4096);
        }
        CP_COMMIT();
        As += TILE; Bs += 65536;
#pragma unroll
        for (int it = 0; it < 4; it++) {
            cp16(A1 + t16 + it * 4096, As + t16 + it * 4096);
            cp16(B1 + t16 + it * 4096, Bs + t16 + it * 4096);
        }
        CP_COMMIT();
    }

    for (int s = 0; s < NSTEP; s += 3) {
        step(s,     A0, B0, A2, B2);
        step(s + 1, A1, B1, A0, B0);
        step(s + 2, A2, B2, A1, B1);
    }

    // ---- epilogue ----
#pragma unroll
    for (int mt = 0; mt < 4; mt++) {
#pragma unroll
        for (int nt = 0; nt < 4; nt++) {
            int m = m0 + wm * 64 + mt * 16 + (l >> 2);
            int n = n0 + wn * 32 + nt * 8 + (l & 3) * 2;
            *(float2*)(out + (size_t)m * OUT_F + n) = make_float2(acc[mt][nt][0], acc[mt][nt][1]);
            *(float2*)(out + (size_t)(m + 8) * OUT_F + n) = make_float2(acc[mt][nt][2], acc[mt][nt][3]);
        }
    }
}

extern "C" void kernel_launch(void* const* d_in, const int* in_sizes, int n_in,
                              void* d_out, int out_size) {
    const float* x    = (const float*)d_in[0];
    const float* bw   = (const float*)d_in[1];
    const float* sw   = (const float*)d_in[2];
    const float* sc   = (const float*)d_in[3];
    const float* grid = (const float*)d_in[4];
    float*       out  = (float*)d_out;

    cudaFuncSetAttribute(kan_mma, cudaFuncAttributeMaxDynamicSharedMemorySize, DYN);

    prep<<<PACK_BLOCKS + SILU_BLOCKS + SPLINE_BLOCKS, 256>>>(bw, sw, sc, x, grid);

    dim3 g(OUT_F / BN, BATCH / BM);   // (4, 128) = 512 CTAs
    kan_mma<<<g, 256, DYN>>>(out);
}